// round 10
// baseline (speedup 1.0000x reference)
#include <cuda_runtime.h>

// S4 DPLR layer, round 10: MUFU elimination. All four-step inter-pass
// twiddles are two-table products (W^mm = hi[mm>>9] * lo[mm&511]) read via
// __ldg instead of __sincosf (which was throughput-bound at MUFU rt=8 and
// set the time of k1/k23/k4). FFT cores identical to verified round-8/9.
//
// Pipeline:
//  k0 : DPLR generator -> dA[k1*512 + m]; blocks 0..3 fill twiddle tables
//  k1 : row IFFT512 of dA + four-step twiddle -> dB     [IFFT_L pass 1]
//  k23: per column pair: IFFT512 (-> K), then forward FFT512 of
//       z = u + i*K for c = m and c = m+512, fwd twiddle -> dA
//  k4 : MEGA: paired rows (k1, 512-k1): fwd FFT1024 x2 (radix-2 split),
//       Hermitian split U,Kd + multiply, inv FFT1024 x2, twiddle -> dB
//  k5 : column IFFT512 of dB, out[n] = Re/2L + D*u[n]  (first L only)

#define L_SIZE   262144   // 2^18
#define N2L      524288   // 2^19
#define PI2      6.283185307179586f
#define RT2      0.70710678118654752f
#define CH       544      // padded smem chunk per 512-pt FFT (float2 units)

__device__ float4 dA4_[N2L/2];    // 4 MB scratch (float4-backed: 16B aligned)
__device__ float4 dB4_[N2L/2];    // 4 MB scratch
#define dA ((float2*)dA4_)
#define dB ((float2*)dB4_)
__device__ float2 gtw512g[512];    // exp(-2pi i k/512)
__device__ float2 gtw1024g[1024];  // exp(-2pi i k/1024)
__device__ float2 gLlo[512];       // exp(-2pi i k/2^18)
__device__ float2 g2Llo[512];      // exp(-2pi i k/2^19)

static __device__ __forceinline__ float2 cmul(float2 a, float2 b) {
    return make_float2(a.x*b.x - a.y*b.y, a.x*b.y + a.y*b.x);
}
static __device__ __forceinline__ float2 cadd(float2 a, float2 b) {
    return make_float2(a.x + b.x, a.y + b.y);
}
static __device__ __forceinline__ float2 csub(float2 a, float2 b) {
    return make_float2(a.x - b.x, a.y - b.y);
}
static __device__ __forceinline__ float2 cfma(float2 a, float2 b, float2 acc) {
    acc.x = fmaf(a.x, b.x, fmaf(-a.y, b.y, acc.x));
    acc.y = fmaf(a.x, b.y, fmaf( a.y, b.x, acc.y));
    return acc;
}

// Four-step twiddles via two-table products (no MUFU).
// exp(-2pi i mm / 2^18):
static __device__ __forceinline__ float2 twL_f(int mm) {
    return cmul(__ldg(&gtw512g[mm >> 9]), __ldg(&gLlo[mm & 511]));
}
// exp(-2pi i mm / 2^19):
static __device__ __forceinline__ float2 tw2L_f(int mm) {
    return cmul(__ldg(&gtw1024g[mm >> 9]), __ldg(&g2Llo[mm & 511]));
}
static __device__ __forceinline__ float2 conj2(float2 a) {
    return make_float2(a.x, -a.y);
}

template<int SIGN>
static __device__ __forceinline__ float2 twl(const float2* tw, int idx) {
    float2 w = tw[idx];
    if (SIGN > 0) w.y = -w.y;
    return w;
}
template<int SIGN>
static __device__ __forceinline__ float2 mulpmi(float2 a) {
    return (SIGN < 0) ? make_float2(a.y, -a.x) : make_float2(-a.y, a.x);
}
template<int SIGN>
static __device__ __forceinline__ float2 mulw81(float2 a) {
    return (SIGN < 0) ? make_float2(RT2*(a.x + a.y), RT2*(a.y - a.x))
                      : make_float2(RT2*(a.x - a.y), RT2*(a.x + a.y));
}
template<int SIGN>
static __device__ __forceinline__ float2 mulw83(float2 a) {
    return (SIGN < 0) ? make_float2(RT2*(a.y - a.x), RT2*(-a.x - a.y))
                      : make_float2(RT2*(-a.x - a.y), RT2*(a.x - a.y));
}

// 8-point FFT in registers, natural order in/out. SIGN=-1 fwd, +1 inv.
template<int SIGN>
static __device__ __forceinline__ void fft8(float2 v[8]) {
    float2 t0 = cadd(v[0], v[4]), t1 = csub(v[0], v[4]);
    float2 t2 = cadd(v[2], v[6]), t3 = mulpmi<SIGN>(csub(v[2], v[6]));
    float2 E0 = cadd(t0, t2), E1 = cadd(t1, t3);
    float2 E2 = csub(t0, t2), E3 = csub(t1, t3);
    float2 u0 = cadd(v[1], v[5]), u1 = csub(v[1], v[5]);
    float2 u2 = cadd(v[3], v[7]), u3 = mulpmi<SIGN>(csub(v[3], v[7]));
    float2 O0 = cadd(u0, u2), O1 = cadd(u1, u3);
    float2 O2 = csub(u0, u2), O3 = csub(u1, u3);
    O1 = mulw81<SIGN>(O1);
    O2 = mulpmi<SIGN>(O2);
    O3 = mulw83<SIGN>(O3);
    v[0] = cadd(E0, O0); v[4] = csub(E0, O0);
    v[1] = cadd(E1, O1); v[5] = csub(E1, O1);
    v[2] = cadd(E2, O2); v[6] = csub(E2, O2);
    v[3] = cadd(E3, O3); v[7] = csub(E3, O3);
}

// 512-pt FFT, 64 threads per FFT (l in [0,64)), 8 points/thread, chunk f at
// offset f*CH in both buffers. Natural input bufA[f*CH+0..511], natural
// output bufB[f*CH+0..511]; bufA clobbered. All block threads MUST call
// (barriers inside); `active` masks work only.
// Layouts: phase1 out: [k0]-stride 66; phase2 out: [n0]-stride 68.
// Every warp access <=2-way conflict. n = 64 n2 + 8 n1 + n0 -> k = k0+8k1+64k2.
template<int SIGN>
static __device__ __forceinline__ void fft512x(
    float2* bufA, float2* bufB, int f, int l, const float2* tw, bool active)
{
    const int base = f * CH;
    float2 v[8];
    if (active) {
        #pragma unroll
        for (int e = 0; e < 8; ++e) v[e] = bufA[base + l + 64*e];
        fft8<SIGN>(v);                               // over n2 -> k0
        const int n1 = l >> 3;
        #pragma unroll
        for (int k0 = 1; k0 < 8; ++k0)               // W64^{n1 k0}
            v[k0] = cmul(v[k0], twl<SIGN>(tw, 8 * n1 * k0));
        #pragma unroll
        for (int k0 = 0; k0 < 8; ++k0) bufB[base + 66*k0 + l] = v[k0];
    }
    __syncthreads();
    {
        const int k0 = l & 7, n0 = l >> 3;
        if (active) {
            #pragma unroll
            for (int n1 = 0; n1 < 8; ++n1) v[n1] = bufB[base + 66*k0 + 8*n1 + n0];
            fft8<SIGN>(v);                           // over n1 -> k1
            #pragma unroll
            for (int k1 = 0; k1 < 8; ++k1)           // W512^{n0 (k0 + 8 k1)}
                v[k1] = cmul(v[k1], twl<SIGN>(tw, n0 * (k0 + 8*k1)));
            #pragma unroll
            for (int k1 = 0; k1 < 8; ++k1) bufA[base + 68*n0 + 8*k1 + k0] = v[k1];
        }
    }
    __syncthreads();
    if (active) {
        #pragma unroll
        for (int n0 = 0; n0 < 8; ++n0) v[n0] = bufA[base + 68*n0 + l];
        fft8<SIGN>(v);                               // over n0 -> k2
        #pragma unroll
        for (int k2 = 0; k2 < 8; ++k2) bufB[base + 64*k2 + l] = v[k2];
    }
    __syncthreads();
}

// ---------------------------------------------------------------------------
// k0: DPLR generator, grid=1024 x 256. 8 rows (k1, per warp) x 32 cols (m,
//     per lane) -> coalesced stores. Omega via sincosf (keeps 1+Omega != 0
//     at Nyquist, matching the f32 reference — tables are exact at pi and
//     would NaN). Pair-batched reciprocals with 2^-24 scaling (overflow-free).
//     Blocks 0..3 fill the global twiddle tables.
// ---------------------------------------------------------------------------
#define TPB0 256
__global__ void k0_gen(const float* __restrict__ Lre, const float* __restrict__ Lim,
                       const float* __restrict__ Pre, const float* __restrict__ Pim,
                       const float* __restrict__ Bre, const float* __restrict__ Bim,
                       const float* __restrict__ Cri, const float* __restrict__ ls) {
    __shared__ float  sLre[64], sLim[64];
    __shared__ float2 sv0[64], sv1[64], sv2[64], sv3[64];
    const int t = threadIdx.x;
    const int b = blockIdx.x;
    if (b == 0) {
        for (int k = t; k < 512; k += TPB0) {
            float s, c; sincospif(-2.0f * (float)k / 512.0f, &s, &c);
            gtw512g[k] = make_float2(c, s);
        }
    } else if (b == 1) {
        for (int k = t; k < 1024; k += TPB0) {
            float s, c; sincospif(-2.0f * (float)k / 1024.0f, &s, &c);
            gtw1024g[k] = make_float2(c, s);
        }
    } else if (b == 2) {
        for (int k = t; k < 512; k += TPB0) {
            float s, c; sincospif(-2.0f * (float)k / 262144.0f, &s, &c);
            gLlo[k] = make_float2(c, s);
        }
    } else if (b == 3) {
        for (int k = t; k < 512; k += TPB0) {
            float s, c; sincospif(-2.0f * (float)k / 524288.0f, &s, &c);
            g2Llo[k] = make_float2(c, s);
        }
    }
    if (t < 64) {
        float2 Pv = make_float2(Pre[t], Pim[t]);
        float2 Bv = make_float2(Bre[t], Bim[t]);
        float2 Cj = make_float2(Cri[2*t], -Cri[2*t+1]);   // conj(C)
        float2 Pj = make_float2(Pv.x, -Pv.y);             // conj(P) (Q = P)
        sLre[t] = Lre[t]; sLim[t] = Lim[t];
        sv0[t] = cmul(Cj, Bv); sv1[t] = cmul(Cj, Pv);
        sv2[t] = cmul(Pj, Bv); sv3[t] = cmul(Pj, Pv);
    }
    __syncthreads();

    const int k1 = (b & 63) * 8 + (t >> 5);
    const int m  = (b >> 6) * 32 + (t & 31);
    const int j  = k1 + (m << 9);
    const float step = expf(ls[0]);

    float ang = -PI2 * ((float)j / (float)L_SIZE);
    float sn, cs; sincosf(ang, &sn, &cs);          // Omega = cs + i*sn
    float2 onem = make_float2(1.f - cs, -sn);
    float2 onep = make_float2(1.f + cs,  sn);
    float invp = 1.f / (onep.x*onep.x + onep.y*onep.y);
    float2 cc = make_float2(2.f*onep.x*invp, -2.f*onep.y*invp);  // 2/(1+Om)
    float2 qv = cmul(onem, make_float2(onep.x, -onep.y));
    float sfac = (2.f / step) * invp;
    float gx = qv.x * sfac, gy = qv.y * sfac;

    const float S = 5.9604644775390625e-8f;        // 2^-24
    float2 k00 = {0,0}, k01 = {0,0}, k10 = {0,0}, k11 = {0,0};
    #pragma unroll
    for (int q = 0; q < 32; ++q) {
        const int n = 2*q;
        float dx0 = gx - sLre[n],   dy0 = gy - sLim[n];
        float dx1 = gx - sLre[n+1], dy1 = gy - sLim[n+1];
        float a0 = fmaf(dx0, dx0, dy0*dy0) * S;
        float a1 = fmaf(dx1, dx1, dy1*dy1) * S;
        float tq = 1.f / (a0 * a1);
        float i0 = a1 * tq * S;                    // = 1/(dx0^2+dy0^2)
        float i1 = a0 * tq * S;
        float2 r0 = make_float2(dx0*i0, -dy0*i0);
        float2 r1 = make_float2(dx1*i1, -dy1*i1);
        k00 = cfma(r0, sv0[n],   k00); k01 = cfma(r0, sv1[n],   k01);
        k10 = cfma(r0, sv2[n],   k10); k11 = cfma(r0, sv3[n],   k11);
        k00 = cfma(r1, sv0[n+1], k00); k01 = cfma(r1, sv1[n+1], k01);
        k10 = cfma(r1, sv2[n+1], k10); k11 = cfma(r1, sv3[n+1], k11);
    }
    float2 den = make_float2(1.f + k11.x, k11.y);
    float invd = 1.f / (den.x*den.x + den.y*den.y);
    float2 num = cmul(k01, k10);
    float2 tq2 = cmul(num, make_float2(den.x*invd, -den.y*invd));
    float2 at  = cmul(cc, make_float2(k00.x - tq2.x, k00.y - tq2.y));

    dA[k1 * 512 + m] = at;
}

// ---------------------------------------------------------------------------
// k1: IFFT_L row pass (2 rows/block, TPB=128) + table twiddle -> dB. grid=256
// ---------------------------------------------------------------------------
#define TPB1 128
__global__ void k1_rowfft() {
    __shared__ __align__(16) float2 sa[2*CH], sb[2*CH];
    __shared__ float2 tw[512];
    const int t = threadIdx.x;
    for (int i = t; i < 512; i += TPB1) tw[i] = gtw512g[i];
    const int row0 = blockIdx.x * 2;
    const float4* src = (const float4*)(dA + row0 * 512);
    for (int i = t; i < 512; i += TPB1) {
        int g = i >> 8, m2 = i & 255;
        float4 x = src[i];
        *(float4*)&sa[g*CH + 2*m2] = x;
    }
    __syncthreads();
    fft512x<+1>(sa, sb, t >> 6, t & 63, tw, true);
    for (int i = t; i < 512; i += TPB1) {
        int g = i >> 8, m2 = i & 255, m = 2*m2;
        int kk = row0 + g;
        float2 y0 = cmul(sb[g*CH + m],     conj2(twL_f((m*kk)     & (L_SIZE-1))));
        float2 y1 = cmul(sb[g*CH + m + 1], conj2(twL_f(((m+1)*kk) & (L_SIZE-1))));
        *(float4*)&dB[kk * 512 + m] = make_float4(y0.x, y0.y, y1.x, y1.y);
    }
}

// ---------------------------------------------------------------------------
// k23 FUSED: columns m0, m0+1 (grid=256, TPB=256).
//   Phase A: IFFT512 of dB cols (2 FFTs, threads<128) -> K; threads>=128
//            prefetch the strided u-gather into smem meanwhile.
//   Phase B: z = u + i*K for c = m and c = m+512; 4 fwd FFTs + fwd table
//            twiddle -> dA[k1*1024 + c].
// ---------------------------------------------------------------------------
#define TPB23 256
__global__ void k23_cols(const float* __restrict__ u) {
    __shared__ __align__(16) float2 sa[4*CH], sb[4*CH];
    __shared__ float2 tw[512];
    __shared__ float su[4*260];
    const int m0 = blockIdx.x * 2;
    const int t = threadIdx.x;
    for (int i = t; i < 512; i += TPB23) tw[i] = gtw512g[i];
    for (int i = t; i < 512; i += TPB23) {
        float4 x = *(const float4*)(dB + i * 512 + m0);
        sa[0*CH + i] = make_float2(x.x, x.y);
        sa[1*CH + i] = make_float2(x.z, x.w);
    }
    __syncthreads();
    if (t >= 128) {
        for (int i = t - 128; i < 1024; i += 128) {
            int fp = i & 3, rr = i >> 2;
            int c = m0 + (fp & 1) + (fp >> 1) * 512;
            su[fp * 260 + rr] = u[rr * 1024 + c];
        }
    }
    fft512x<+1>(sa, sb, t >> 6, t & 63, tw, t < 128);
    const float invL = 1.0f / (float)L_SIZE;
    for (int i = t; i < 2048; i += TPB23) {
        int fp = i >> 9, rr = i & 511;
        int half = fp >> 1, f = fp & 1;
        float2 z = make_float2(0.f, 0.f);
        if (rr < 256) {
            float kv = sb[f*CH + 2*rr + half].x * invL;
            z = make_float2(su[fp * 260 + rr], kv);
        }
        sa[fp*CH + rr] = z;
    }
    __syncthreads();
    fft512x<-1>(sa, sb, t >> 6, t & 63, tw, true);
    for (int i = t; i < 2048; i += TPB23) {
        int fp = i & 3, k1 = i >> 2;
        int half = fp >> 1, f = fp & 1;
        int c = m0 + f + half * 512;
        int mm = (c * k1) & (N2L - 1);
        dA[k1 * 1024 + c] = cmul(sb[fp*CH + k1], tw2L_f(mm));
    }
}

// ---------------------------------------------------------------------------
// k4 MEGA: paired rows (k1, 512-k1); block 0 takes self-paired rows {0,256}.
//   FFT1024 as radix-2 split: X[2r+h] = FFT512 of (a +/- b [*W1024^m]).
//   Chunk fp = slot*2 + h holds Z[2r+h] of row slot. Hermitian pointwise,
//   2x IFFT512 per slot, combine, inv table twiddle -> dB. grid=256, TPB=256.
// ---------------------------------------------------------------------------
#define TPB4 256
__global__ void k4_mega() {
    __shared__ __align__(16) float2 sa[4*CH], sb[4*CH];
    __shared__ float2 tw[512], twh[512];
    const int t = threadIdx.x;
    for (int i = t; i < 512; i += TPB4) { tw[i] = gtw512g[i]; twh[i] = gtw1024g[i]; }
    const int b = blockIdx.x;
    const int rowA = b;
    const int rowB = (b == 0) ? 256 : 512 - b;

    for (int i = t; i < 1024; i += TPB4) {
        int slot = i >> 9, m2 = i & 511;
        int row = slot ? rowB : rowA;
        float4 x = ((const float4*)(dA + row * 1024))[m2];
        *(float4*)&sb[slot * 1024 + 2*m2] = x;
    }
    __syncthreads();
    for (int i = t; i < 1024; i += TPB4) {
        int slot = i >> 9, m = i & 511;
        float2 a = sb[slot * 1024 + m];
        float2 c = sb[slot * 1024 + m + 512];
        sa[(slot*2 + 0)*CH + m] = cadd(a, c);
        sa[(slot*2 + 1)*CH + m] = cmul(csub(a, c), twh[m]);
    }
    __syncthreads();
    fft512x<-1>(sa, sb, t >> 6, t & 63, tw, true);
    for (int i = t; i < 2048; i += TPB4) {
        int fp = i >> 9, r = i & 511;
        int slot = fp >> 1, h = fp & 1;
        int k = 2*r + h;
        int pslot, pk;
        if (b == 0) {
            pslot = slot;
            pk = slot ? (1023 - k) : ((1024 - k) & 1023);
        } else {
            pslot = 1 - slot;
            pk = 1023 - k;
        }
        float2 Zv = sb[fp*CH + r];
        float2 Zp = sb[(pslot*2 + (pk & 1))*CH + (pk >> 1)];
        float2 U  = make_float2(0.5f * (Zv.x + Zp.x),  0.5f * (Zv.y - Zp.y));
        float2 Kd = make_float2(0.5f * (Zv.y + Zp.y), -0.5f * (Zv.x - Zp.x));
        sa[fp*CH + r] = cmul(U, Kd);
    }
    __syncthreads();
    fft512x<+1>(sa, sb, t >> 6, t & 63, tw, true);
    for (int i = t; i < 1024; i += TPB4) {
        int slot = i >> 9, m = i & 511;
        float2 E = sb[(slot*2 + 0)*CH + m];
        float2 O = sb[(slot*2 + 1)*CH + m];
        float2 Vm = make_float2(twh[m].x, -twh[m].y);   // conj
        float2 w  = cmul(Vm, O);
        float2 y0 = cadd(E, w);
        float2 y1 = csub(E, w);
        int kk = slot ? rowB : rowA;
        int mm0 = (m * kk) & (N2L - 1);
        int mm1 = ((m + 512) * kk) & (N2L - 1);
        dB[kk * 1024 + m]       = cmul(y0, conj2(tw2L_f(mm0)));
        dB[kk * 1024 + m + 512] = cmul(y1, conj2(tw2L_f(mm1)));
    }
}

// ---------------------------------------------------------------------------
// k5: inverse column FFTs (4 cols/block); out[n] = Re/2L + D*u[n],
//     only first 256 rows (n < L). grid=256
// ---------------------------------------------------------------------------
#define TPB5 256
__global__ void k5_inv_cols(const float* __restrict__ u, const float* __restrict__ Dp,
                            float* __restrict__ out) {
    __shared__ __align__(16) float2 sa[4*CH], sb[4*CH];
    __shared__ float2 tw[512];
    const int c0 = blockIdx.x * 4;
    const int t = threadIdx.x;
    for (int i = t; i < 512; i += TPB5) tw[i] = gtw512g[i];
    for (int i = t; i < 1024; i += TPB5) {
        int rr = i >> 1, gg = i & 1;
        float4 x = ((const float4*)(dB + rr * 1024 + c0))[gg];
        sa[(2*gg  )*CH + rr] = make_float2(x.x, x.y);
        sa[(2*gg+1)*CH + rr] = make_float2(x.z, x.w);
    }
    __syncthreads();
    fft512x<+1>(sa, sb, t >> 6, t & 63, tw, true);
    const float sc = 1.0f / (float)N2L;
    const float Dv = Dp[0];
    for (int p = t; p < 256; p += TPB5) {
        float4 uu = *(const float4*)(u + p * 1024 + c0);
        float4 o;
        o.x = fmaf(Dv, uu.x, sb[0*CH + p].x * sc);
        o.y = fmaf(Dv, uu.y, sb[1*CH + p].x * sc);
        o.z = fmaf(Dv, uu.z, sb[2*CH + p].x * sc);
        o.w = fmaf(Dv, uu.w, sb[3*CH + p].x * sc);
        *(float4*)(out + p * 1024 + c0) = o;
    }
}

// ---------------------------------------------------------------------------
extern "C" void kernel_launch(void* const* d_in, const int* in_sizes, int n_in,
                              void* d_out, int out_size) {
    (void)in_sizes; (void)n_in; (void)out_size;
    const float* u   = (const float*)d_in[0];
    const float* Lre = (const float*)d_in[1];
    const float* Lim = (const float*)d_in[2];
    const float* Pre = (const float*)d_in[3];
    const float* Pim = (const float*)d_in[4];
    const float* Bre = (const float*)d_in[5];
    const float* Bim = (const float*)d_in[6];
    const float* Cri = (const float*)d_in[7];
    const float* Dp  = (const float*)d_in[8];
    const float* ls  = (const float*)d_in[9];
    float* out = (float*)d_out;

    k0_gen      <<<1024, TPB0>>>(Lre, Lim, Pre, Pim, Bre, Bim, Cri, ls);
    k1_rowfft   <<<256,  TPB1>>>();
    k23_cols    <<<256,  TPB23>>>(u);
    k4_mega     <<<256,  TPB4>>>();
    k5_inv_cols <<<256,  TPB5>>>(u, Dp, out);
}

// round 11
// speedup vs baseline: 1.0795x; 1.0795x over previous
#include <cuda_runtime.h>

// S4 DPLR layer, round 11: real-output half-size inverse. Since S = U*Kd is
// exactly Hermitian, the final inverse is done as ONE L-point complex IFFT of
// T[k] = (S[k]+S[k+L])/2 + i*w^k (S[k]-S[k+L])/2  (w = e^{+2pi i/2L}),
// giving z2[m] = y[2m] + i y[2m+1]. k4's inverse halves (2 FFT512s instead of
// 4), k5 halves (512 columns instead of 1024). Twiddles back to __sincosf
// (R10's table products regressed). FFT core = verified conflict-engineered
// radix-8 (<=2-way on every smem access).
//
// Pipeline:
//  k0 : DPLR generator -> dA[k1*512 + m]; blocks 0,1 fill twiddle tables
//  k1 : row IFFT512 of dA + four-step twiddle -> dB     [IFFT_L pass 1]
//  k23: per column pair: IFFT512 (-> K), then forward FFT512 of
//       z = u + i*K for c = m and c = m+512, fwd twiddle -> dA
//  k4 : paired rows (k1, 512-k1): fwd FFT1024 x2 (radix-2 split), Hermitian
//       split U,Kd + multiply -> S; build T row; FFT512 + W_L twiddle -> dB
//       (dB now a 512x512 matrix)
//  k5 : column IFFT512 of dB; out[2n] = Re/L + D*u[2n], out[2n+1] = Im/L + ...

#define L_SIZE   262144   // 2^18
#define N2L      524288   // 2^19
#define PI2      6.283185307179586f
#define RT2      0.70710678118654752f
#define CH       544      // padded smem chunk per 512-pt FFT (float2 units)

__device__ float4 dA4_[N2L/2];    // 4 MB scratch (float4-backed: 16B aligned)
__device__ float4 dB4_[N2L/2];    // 4 MB scratch
#define dA ((float2*)dA4_)
#define dB ((float2*)dB4_)
__device__ float2 gtw512g[512];    // exp(-2pi i k/512)
__device__ float2 gtw1024g[512];   // exp(-2pi i k/1024), k<512

static __device__ __forceinline__ float2 cmul(float2 a, float2 b) {
    return make_float2(a.x*b.x - a.y*b.y, a.x*b.y + a.y*b.x);
}
static __device__ __forceinline__ float2 cadd(float2 a, float2 b) {
    return make_float2(a.x + b.x, a.y + b.y);
}
static __device__ __forceinline__ float2 csub(float2 a, float2 b) {
    return make_float2(a.x - b.x, a.y - b.y);
}
static __device__ __forceinline__ float2 cfma(float2 a, float2 b, float2 acc) {
    acc.x = fmaf(a.x, b.x, fmaf(-a.y, b.y, acc.x));
    acc.y = fmaf(a.x, b.y, fmaf( a.y, b.x, acc.y));
    return acc;
}

// exp(sgn * 2*pi*i * mm / n), mm in [0, n). Centered arg -> __sincosf safe.
static __device__ __forceinline__ float2 twiddle_c(int mm, int n, float sgn) {
    int tt = mm - ((mm >= (n >> 1)) ? n : 0);
    float ang = sgn * (PI2 / (float)n) * (float)tt;
    float s, c; __sincosf(ang, &s, &c);
    return make_float2(c, s);
}

template<int SIGN>
static __device__ __forceinline__ float2 twl(const float2* tw, int idx) {
    float2 w = tw[idx];
    if (SIGN > 0) w.y = -w.y;
    return w;
}
template<int SIGN>
static __device__ __forceinline__ float2 mulpmi(float2 a) {
    return (SIGN < 0) ? make_float2(a.y, -a.x) : make_float2(-a.y, a.x);
}
template<int SIGN>
static __device__ __forceinline__ float2 mulw81(float2 a) {
    return (SIGN < 0) ? make_float2(RT2*(a.x + a.y), RT2*(a.y - a.x))
                      : make_float2(RT2*(a.x - a.y), RT2*(a.x + a.y));
}
template<int SIGN>
static __device__ __forceinline__ float2 mulw83(float2 a) {
    return (SIGN < 0) ? make_float2(RT2*(a.y - a.x), RT2*(-a.x - a.y))
                      : make_float2(RT2*(-a.x - a.y), RT2*(a.x - a.y));
}

// 8-point FFT in registers, natural order in/out. SIGN=-1 fwd, +1 inv.
template<int SIGN>
static __device__ __forceinline__ void fft8(float2 v[8]) {
    float2 t0 = cadd(v[0], v[4]), t1 = csub(v[0], v[4]);
    float2 t2 = cadd(v[2], v[6]), t3 = mulpmi<SIGN>(csub(v[2], v[6]));
    float2 E0 = cadd(t0, t2), E1 = cadd(t1, t3);
    float2 E2 = csub(t0, t2), E3 = csub(t1, t3);
    float2 u0 = cadd(v[1], v[5]), u1 = csub(v[1], v[5]);
    float2 u2 = cadd(v[3], v[7]), u3 = mulpmi<SIGN>(csub(v[3], v[7]));
    float2 O0 = cadd(u0, u2), O1 = cadd(u1, u3);
    float2 O2 = csub(u0, u2), O3 = csub(u1, u3);
    O1 = mulw81<SIGN>(O1);
    O2 = mulpmi<SIGN>(O2);
    O3 = mulw83<SIGN>(O3);
    v[0] = cadd(E0, O0); v[4] = csub(E0, O0);
    v[1] = cadd(E1, O1); v[5] = csub(E1, O1);
    v[2] = cadd(E2, O2); v[6] = csub(E2, O2);
    v[3] = cadd(E3, O3); v[7] = csub(E3, O3);
}

// 512-pt FFT, 64 threads per FFT (l in [0,64)), 8 points/thread, chunk f at
// offset f*CH in both buffers. Natural input bufA[f*CH+0..511], natural
// output bufB[f*CH+0..511]; bufA clobbered. All block threads MUST call
// (barriers inside); `active` masks work only. Caller syncs after fill.
// Layouts: phase1 out: [k0]-stride 66; phase2 out: [n0]-stride 68.
template<int SIGN>
static __device__ __forceinline__ void fft512x(
    float2* bufA, float2* bufB, int f, int l, const float2* tw, bool active)
{
    const int base = f * CH;
    float2 v[8];
    if (active) {
        #pragma unroll
        for (int e = 0; e < 8; ++e) v[e] = bufA[base + l + 64*e];
        fft8<SIGN>(v);                               // over n2 -> k0
        const int n1 = l >> 3;
        #pragma unroll
        for (int k0 = 1; k0 < 8; ++k0)               // W64^{n1 k0}
            v[k0] = cmul(v[k0], twl<SIGN>(tw, 8 * n1 * k0));
        #pragma unroll
        for (int k0 = 0; k0 < 8; ++k0) bufB[base + 66*k0 + l] = v[k0];
    }
    __syncthreads();
    {
        const int k0 = l & 7, n0 = l >> 3;
        if (active) {
            #pragma unroll
            for (int n1 = 0; n1 < 8; ++n1) v[n1] = bufB[base + 66*k0 + 8*n1 + n0];
            fft8<SIGN>(v);                           // over n1 -> k1
            #pragma unroll
            for (int k1 = 0; k1 < 8; ++k1)           // W512^{n0 (k0 + 8 k1)}
                v[k1] = cmul(v[k1], twl<SIGN>(tw, n0 * (k0 + 8*k1)));
            #pragma unroll
            for (int k1 = 0; k1 < 8; ++k1) bufA[base + 68*n0 + 8*k1 + k0] = v[k1];
        }
    }
    __syncthreads();
    if (active) {
        #pragma unroll
        for (int n0 = 0; n0 < 8; ++n0) v[n0] = bufA[base + 68*n0 + l];
        fft8<SIGN>(v);                               // over n0 -> k2
        #pragma unroll
        for (int k2 = 0; k2 < 8; ++k2) bufB[base + 64*k2 + l] = v[k2];
    }
    __syncthreads();
}

// ---------------------------------------------------------------------------
// k0: DPLR generator, grid=1024 x 256. 8 rows (k1, per warp) x 32 cols (m,
//     per lane) -> coalesced stores. Omega via sincosf (keeps 1+Omega != 0
//     at Nyquist, matching the f32 reference). Pair-batched reciprocals with
//     2^-24 scaling (overflow-free). Blocks 0,1 fill global twiddle tables.
// ---------------------------------------------------------------------------
#define TPB0 256
__global__ void k0_gen(const float* __restrict__ Lre, const float* __restrict__ Lim,
                       const float* __restrict__ Pre, const float* __restrict__ Pim,
                       const float* __restrict__ Bre, const float* __restrict__ Bim,
                       const float* __restrict__ Cri, const float* __restrict__ ls) {
    __shared__ float  sLre[64], sLim[64];
    __shared__ float2 sv0[64], sv1[64], sv2[64], sv3[64];
    const int t = threadIdx.x;
    const int b = blockIdx.x;
    if (b == 0) {
        for (int k = t; k < 512; k += TPB0) {
            float s, c; sincospif(-2.0f * (float)k / 512.0f, &s, &c);
            gtw512g[k] = make_float2(c, s);
        }
    } else if (b == 1) {
        for (int k = t; k < 512; k += TPB0) {
            float s, c; sincospif(-2.0f * (float)k / 1024.0f, &s, &c);
            gtw1024g[k] = make_float2(c, s);
        }
    }
    if (t < 64) {
        float2 Pv = make_float2(Pre[t], Pim[t]);
        float2 Bv = make_float2(Bre[t], Bim[t]);
        float2 Cj = make_float2(Cri[2*t], -Cri[2*t+1]);   // conj(C)
        float2 Pj = make_float2(Pv.x, -Pv.y);             // conj(P) (Q = P)
        sLre[t] = Lre[t]; sLim[t] = Lim[t];
        sv0[t] = cmul(Cj, Bv); sv1[t] = cmul(Cj, Pv);
        sv2[t] = cmul(Pj, Bv); sv3[t] = cmul(Pj, Pv);
    }
    __syncthreads();

    const int k1 = (b & 63) * 8 + (t >> 5);
    const int m  = (b >> 6) * 32 + (t & 31);
    const int j  = k1 + (m << 9);
    const float step = expf(ls[0]);

    float ang = -PI2 * ((float)j / (float)L_SIZE);
    float sn, cs; sincosf(ang, &sn, &cs);          // Omega = cs + i*sn
    float2 onem = make_float2(1.f - cs, -sn);
    float2 onep = make_float2(1.f + cs,  sn);
    float invp = 1.f / (onep.x*onep.x + onep.y*onep.y);
    float2 cc = make_float2(2.f*onep.x*invp, -2.f*onep.y*invp);  // 2/(1+Om)
    float2 qv = cmul(onem, make_float2(onep.x, -onep.y));
    float sfac = (2.f / step) * invp;
    float gx = qv.x * sfac, gy = qv.y * sfac;

    const float S = 5.9604644775390625e-8f;        // 2^-24
    float2 k00 = {0,0}, k01 = {0,0}, k10 = {0,0}, k11 = {0,0};
    #pragma unroll
    for (int q = 0; q < 32; ++q) {
        const int n = 2*q;
        float dx0 = gx - sLre[n],   dy0 = gy - sLim[n];
        float dx1 = gx - sLre[n+1], dy1 = gy - sLim[n+1];
        float a0 = fmaf(dx0, dx0, dy0*dy0) * S;
        float a1 = fmaf(dx1, dx1, dy1*dy1) * S;
        float tq = 1.f / (a0 * a1);
        float i0 = a1 * tq * S;                    // = 1/(dx0^2+dy0^2)
        float i1 = a0 * tq * S;
        float2 r0 = make_float2(dx0*i0, -dy0*i0);
        float2 r1 = make_float2(dx1*i1, -dy1*i1);
        k00 = cfma(r0, sv0[n],   k00); k01 = cfma(r0, sv1[n],   k01);
        k10 = cfma(r0, sv2[n],   k10); k11 = cfma(r0, sv3[n],   k11);
        k00 = cfma(r1, sv0[n+1], k00); k01 = cfma(r1, sv1[n+1], k01);
        k10 = cfma(r1, sv2[n+1], k10); k11 = cfma(r1, sv3[n+1], k11);
    }
    float2 den = make_float2(1.f + k11.x, k11.y);
    float invd = 1.f / (den.x*den.x + den.y*den.y);
    float2 num = cmul(k01, k10);
    float2 tq2 = cmul(num, make_float2(den.x*invd, -den.y*invd));
    float2 at  = cmul(cc, make_float2(k00.x - tq2.x, k00.y - tq2.y));

    dA[k1 * 512 + m] = at;
}

// ---------------------------------------------------------------------------
// k1: IFFT_L row pass (2 rows/block, TPB=128) + twiddle -> dB. grid=256
// ---------------------------------------------------------------------------
#define TPB1 128
__global__ void k1_rowfft() {
    __shared__ __align__(16) float2 sa[2*CH], sb[2*CH];
    __shared__ float2 tw[512];
    const int t = threadIdx.x;
    for (int i = t; i < 512; i += TPB1) tw[i] = gtw512g[i];
    const int row0 = blockIdx.x * 2;
    const float4* src = (const float4*)(dA + row0 * 512);
    for (int i = t; i < 512; i += TPB1) {
        int g = i >> 8, m2 = i & 255;
        float4 x = src[i];
        *(float4*)&sa[g*CH + 2*m2] = x;
    }
    __syncthreads();
    fft512x<+1>(sa, sb, t >> 6, t & 63, tw, true);
    for (int i = t; i < 512; i += TPB1) {
        int g = i >> 8, m2 = i & 255, m = 2*m2;
        int kk = row0 + g;
        float2 y0 = cmul(sb[g*CH + m],     twiddle_c((m*kk) & (L_SIZE-1),     L_SIZE, 1.0f));
        float2 y1 = cmul(sb[g*CH + m + 1], twiddle_c(((m+1)*kk) & (L_SIZE-1), L_SIZE, 1.0f));
        *(float4*)&dB[kk * 512 + m] = make_float4(y0.x, y0.y, y1.x, y1.y);
    }
}

// ---------------------------------------------------------------------------
// k23 FUSED: columns m0, m0+1 (grid=256, TPB=256).
//   Phase A: IFFT512 of dB cols (2 FFTs, threads<128) -> K; threads>=128
//            prefetch the strided u-gather into smem meanwhile.
//   Phase B: z = u + i*K for c = m and c = m+512; 4 fwd FFTs + fwd twiddle
//            -> dA[k1*1024 + c].
// ---------------------------------------------------------------------------
#define TPB23 256
__global__ void k23_cols(const float* __restrict__ u) {
    __shared__ __align__(16) float2 sa[4*CH], sb[4*CH];
    __shared__ float2 tw[512];
    __shared__ float su[4*260];
    const int m0 = blockIdx.x * 2;
    const int t = threadIdx.x;
    for (int i = t; i < 512; i += TPB23) tw[i] = gtw512g[i];
    for (int i = t; i < 512; i += TPB23) {
        float4 x = *(const float4*)(dB + i * 512 + m0);
        sa[0*CH + i] = make_float2(x.x, x.y);
        sa[1*CH + i] = make_float2(x.z, x.w);
    }
    __syncthreads();
    if (t >= 128) {
        for (int i = t - 128; i < 1024; i += 128) {
            int fp = i & 3, rr = i >> 2;
            int c = m0 + (fp & 1) + (fp >> 1) * 512;
            su[fp * 260 + rr] = u[rr * 1024 + c];
        }
    }
    fft512x<+1>(sa, sb, t >> 6, t & 63, tw, t < 128);
    const float invL = 1.0f / (float)L_SIZE;
    for (int i = t; i < 2048; i += TPB23) {
        int fp = i >> 9, rr = i & 511;
        int half = fp >> 1, f = fp & 1;
        float2 z = make_float2(0.f, 0.f);
        if (rr < 256) {
            float kv = sb[f*CH + 2*rr + half].x * invL;
            z = make_float2(su[fp * 260 + rr], kv);
        }
        sa[fp*CH + rr] = z;
    }
    __syncthreads();
    fft512x<-1>(sa, sb, t >> 6, t & 63, tw, true);
    for (int i = t; i < 2048; i += TPB23) {
        int fp = i & 3, k1 = i >> 2;
        int half = fp >> 1, f = fp & 1;
        int c = m0 + f + half * 512;
        int mm = (c * k1) & (N2L - 1);
        dA[k1 * 1024 + c] = cmul(sb[fp*CH + k1], twiddle_c(mm, N2L, -1.0f));
    }
}

// ---------------------------------------------------------------------------
// k4: paired rows (k1, 512-k1); block 0 takes self-paired rows {0,256}.
//   fwd FFT1024 x2 via radix-2 split (chunk fp = slot*2+h holds Z[2r+h]).
//   Pointwise S = U*Kd (Hermitian split). Then the REAL-OUTPUT trick:
//   T[kc] = (S[k]+S[k+L])/2 + i w^k (S[k]-S[k+L])/2, k = rowk1 + 512 kc,
//   w = e^{+2pi i/2L}. One FFT512^{+} per slot on T + W_L^{+m k1} twiddle
//   -> dB[k1*512 + m]   (dB = 512x512 L-point four-step intermediate).
// ---------------------------------------------------------------------------
#define TPB4 256
__global__ void k4_mega() {
    __shared__ __align__(16) float2 sa[4*CH], sb[4*CH];
    __shared__ float2 tw[512], twh[512];
    const int t = threadIdx.x;
    for (int i = t; i < 512; i += TPB4) { tw[i] = gtw512g[i]; twh[i] = gtw1024g[i]; }
    const int b = blockIdx.x;
    const int rowA = b;
    const int rowB = (b == 0) ? 256 : 512 - b;

    for (int i = t; i < 1024; i += TPB4) {
        int slot = i >> 9, m2 = i & 511;
        int row = slot ? rowB : rowA;
        float4 x = ((const float4*)(dA + row * 1024))[m2];
        *(float4*)&sb[slot * 1024 + 2*m2] = x;
    }
    __syncthreads();
    // radix-2 pre-stage into chunks fp = slot*2 + h
    for (int i = t; i < 1024; i += TPB4) {
        int slot = i >> 9, m = i & 511;
        float2 a = sb[slot * 1024 + m];
        float2 c = sb[slot * 1024 + m + 512];
        sa[(slot*2 + 0)*CH + m] = cadd(a, c);
        sa[(slot*2 + 1)*CH + m] = cmul(csub(a, c), twh[m]);
    }
    __syncthreads();
    fft512x<-1>(sa, sb, t >> 6, t & 63, tw, true);
    // sb chunk fp, pos r  <->  Z[2r + (fp&1)] of row slot = fp>>1.
    // Pointwise S = U*Kd -> sa (same layout).
    for (int i = t; i < 2048; i += TPB4) {
        int fp = i >> 9, r = i & 511;
        int slot = fp >> 1, h = fp & 1;
        int k = 2*r + h;
        int pslot, pk;
        if (b == 0) {
            pslot = slot;
            pk = slot ? (1023 - k) : ((1024 - k) & 1023);
        } else {
            pslot = 1 - slot;
            pk = 1023 - k;
        }
        float2 Zv = sb[fp*CH + r];
        float2 Zp = sb[(pslot*2 + (pk & 1))*CH + (pk >> 1)];
        float2 U  = make_float2(0.5f * (Zv.x + Zp.x),  0.5f * (Zv.y - Zp.y));
        float2 Kd = make_float2(0.5f * (Zv.y + Zp.y), -0.5f * (Zv.x - Zp.x));
        sa[fp*CH + r] = cmul(U, Kd);
    }
    __syncthreads();
    // Build T rows: S[k1+512 kc] at chunk (slot*2 + (kc&1)), pos kc>>1;
    // S[k1+512(kc+512)] at same chunk, pos (kc>>1)+256. T -> sb chunk slot.
    for (int i = t; i < 1024; i += TPB4) {
        int slot = i >> 9, kc = i & 511;
        int h = kc & 1, r0 = kc >> 1;
        int cb = (slot*2 + h)*CH;
        float2 S1 = sa[cb + r0];
        float2 S2 = sa[cb + r0 + 256];
        float2 E = make_float2(0.5f*(S1.x + S2.x), 0.5f*(S1.y + S2.y));
        float2 d = make_float2(0.5f*(S1.x - S2.x), 0.5f*(S1.y - S2.y));
        int kk = slot ? rowB : rowA;
        float2 o = cmul(twiddle_c(kk + (kc << 9), N2L, 1.0f), d);   // w^k * d
        sb[slot*CH + kc] = make_float2(E.x - o.y, E.y + o.x);       // E + i*O
    }
    __syncthreads();
    fft512x<+1>(sb, sa, t >> 6, t & 63, tw, t < 128);   // out in sa chunks 0,1
    for (int i = t; i < 1024; i += TPB4) {
        int slot = i >> 9, m = i & 511;
        int kk = slot ? rowB : rowA;
        dB[kk * 512 + m] = cmul(sa[slot*CH + m],
                                twiddle_c((m*kk) & (L_SIZE-1), L_SIZE, 1.0f));
    }
}

// ---------------------------------------------------------------------------
// k5: column IFFT512 of the 512x512 matrix dB (2 cols/block, TPB=128,
//     grid=256). z2[p*512+m] = y[2n] + i y[2n+1], n = p*512+m, p < 256.
//     out[2n..2n+3] written as one float4 combining both columns.
// ---------------------------------------------------------------------------
#define TPB5 128
__global__ void k5_inv_cols(const float* __restrict__ u, const float* __restrict__ Dp,
                            float* __restrict__ out) {
    __shared__ __align__(16) float2 sa[2*CH], sb[2*CH];
    __shared__ float2 tw[512];
    const int m0 = blockIdx.x * 2;
    const int t = threadIdx.x;
    for (int i = t; i < 512; i += TPB5) tw[i] = gtw512g[i];
    for (int i = t; i < 512; i += TPB5) {
        float4 x = *(const float4*)(dB + i * 512 + m0);
        sa[0*CH + i] = make_float2(x.x, x.y);
        sa[1*CH + i] = make_float2(x.z, x.w);
    }
    __syncthreads();
    fft512x<+1>(sa, sb, t >> 6, t & 63, tw, true);
    const float sc = 1.0f / (float)L_SIZE;
    const float Dv = Dp[0];
    for (int p = t; p < 256; p += TPB5) {
        float2 v0 = sb[0*CH + p];     // column m0   -> y[2n0], y[2n0+1]
        float2 v1 = sb[1*CH + p];     // column m0+1 -> y[2n0+2], y[2n0+3]
        int n2 = 2 * (p * 512 + m0);  // = 2*n0, 16B-aligned (m0 even)
        float4 uu = *(const float4*)(u + n2);
        float4 o;
        o.x = fmaf(Dv, uu.x, v0.x * sc);
        o.y = fmaf(Dv, uu.y, v0.y * sc);
        o.z = fmaf(Dv, uu.z, v1.x * sc);
        o.w = fmaf(Dv, uu.w, v1.y * sc);
        *(float4*)(out + n2) = o;
    }
}

// ---------------------------------------------------------------------------
extern "C" void kernel_launch(void* const* d_in, const int* in_sizes, int n_in,
                              void* d_out, int out_size) {
    (void)in_sizes; (void)n_in; (void)out_size;
    const float* u   = (const float*)d_in[0];
    const float* Lre = (const float*)d_in[1];
    const float* Lim = (const float*)d_in[2];
    const float* Pre = (const float*)d_in[3];
    const float* Pim = (const float*)d_in[4];
    const float* Bre = (const float*)d_in[5];
    const float* Bim = (const float*)d_in[6];
    const float* Cri = (const float*)d_in[7];
    const float* Dp  = (const float*)d_in[8];
    const float* ls  = (const float*)d_in[9];
    float* out = (float*)d_out;

    k0_gen      <<<1024, TPB0>>>(Lre, Lim, Pre, Pim, Bre, Bim, Cri, ls);
    k1_rowfft   <<<256,  TPB1>>>();
    k23_cols    <<<256,  TPB23>>>(u);
    k4_mega     <<<256,  TPB4>>>();
    k5_inv_cols <<<256,  TPB5>>>(u, Dp, out);
}

// round 12
// speedup vs baseline: 1.0855x; 1.0056x over previous
#include <cuda_runtime.h>

// S4 DPLR layer, round 12: packed f32x2 arithmetic (fma.rn.f32x2 etc.) in the
// FFT butterflies and the generator's pole loop; per-FFT named barriers
// (bar.sync id,64) so 64-thread FFT groups don't align block-wide.
// Structure identical to round-11 (half-size real-output inverse).

#define L_SIZE   262144   // 2^18
#define N2L      524288   // 2^19
#define PI2      6.283185307179586f
#define RT2      0.70710678118654752f
#define CH       544      // padded smem chunk per 512-pt FFT (float2 units)

__device__ float4 dA4_[N2L/2];    // 4 MB scratch (float4-backed: 16B aligned)
__device__ float4 dB4_[N2L/2];    // 4 MB scratch
#define dA ((float2*)dA4_)
#define dB ((float2*)dB4_)
__device__ float2 gtw512g[512];    // exp(-2pi i k/512)
__device__ float2 gtw1024g[512];   // exp(-2pi i k/1024), k<512

typedef unsigned long long u64c;
#define NEG1P 0xBF800000BF800000ull   // packed (-1.0f, -1.0f)

static __device__ __forceinline__ u64c pk(float2 a) {
    u64c r; asm("mov.b64 %0, {%1, %2};" : "=l"(r) : "f"(a.x), "f"(a.y)); return r;
}
static __device__ __forceinline__ float2 upk(u64c a) {
    float2 r; asm("mov.b64 {%0, %1}, %2;" : "=f"(r.x), "=f"(r.y) : "l"(a)); return r;
}
static __device__ __forceinline__ u64c padd(u64c a, u64c b) {
    u64c r; asm("add.rn.f32x2 %0, %1, %2;" : "=l"(r) : "l"(a), "l"(b)); return r;
}
static __device__ __forceinline__ u64c pmul(u64c a, u64c b) {
    u64c r; asm("mul.rn.f32x2 %0, %1, %2;" : "=l"(r) : "l"(a), "l"(b)); return r;
}
static __device__ __forceinline__ u64c pfma(u64c a, u64c b, u64c c) {
    u64c r; asm("fma.rn.f32x2 %0, %1, %2, %3;" : "=l"(r) : "l"(a), "l"(b), "l"(c)); return r;
}
// a - b  ==  fma(b, -1, a)  (exact: -1*b exact, single rounding)
static __device__ __forceinline__ u64c psub(u64c a, u64c b) {
    u64c r; asm("fma.rn.f32x2 %0, %1, %2, %3;" : "=l"(r) : "l"(b), "l"((u64c)NEG1P), "l"(a)); return r;
}

static __device__ __forceinline__ float2 cmul(float2 a, float2 b) {
    return make_float2(a.x*b.x - a.y*b.y, a.x*b.y + a.y*b.x);
}
static __device__ __forceinline__ float2 cadd(float2 a, float2 b) {
    return make_float2(a.x + b.x, a.y + b.y);
}
static __device__ __forceinline__ float2 csub(float2 a, float2 b) {
    return make_float2(a.x - b.x, a.y - b.y);
}

// exp(sgn * 2*pi*i * mm / n), mm in [0, n). Centered arg -> __sincosf safe.
static __device__ __forceinline__ float2 twiddle_c(int mm, int n, float sgn) {
    int tt = mm - ((mm >= (n >> 1)) ? n : 0);
    float ang = sgn * (PI2 / (float)n) * (float)tt;
    float s, c; __sincosf(ang, &s, &c);
    return make_float2(c, s);
}

template<int SIGN>
static __device__ __forceinline__ float2 twl(const float2* tw, int idx) {
    float2 w = tw[idx];
    if (SIGN > 0) w.y = -w.y;
    return w;
}
// packed-complex * float2 twiddle (scalar core)
static __device__ __forceinline__ u64c pcmul(u64c a, float2 b) {
    float2 f = upk(a);
    return pk(cmul(f, b));
}
template<int SIGN>
static __device__ __forceinline__ u64c pmulpmi(u64c a) {   // *(-i) fwd, *(+i) inv
    float2 f = upk(a);
    return (SIGN < 0) ? pk(make_float2(f.y, -f.x)) : pk(make_float2(-f.y, f.x));
}
template<int SIGN>
static __device__ __forceinline__ u64c pmulw81(u64c a) {
    float2 f = upk(a);
    return (SIGN < 0) ? pk(make_float2(RT2*(f.x + f.y), RT2*(f.y - f.x)))
                      : pk(make_float2(RT2*(f.x - f.y), RT2*(f.x + f.y)));
}
template<int SIGN>
static __device__ __forceinline__ u64c pmulw83(u64c a) {
    float2 f = upk(a);
    return (SIGN < 0) ? pk(make_float2(RT2*(f.y - f.x), RT2*(-f.x - f.y)))
                      : pk(make_float2(RT2*(-f.x - f.y), RT2*(f.x - f.y)));
}

// 8-point FFT on packed complex, natural order. SIGN=-1 fwd, +1 inv.
template<int SIGN>
static __device__ __forceinline__ void fft8p(u64c v[8]) {
    u64c t0 = padd(v[0], v[4]), t1 = psub(v[0], v[4]);
    u64c t2 = padd(v[2], v[6]), t3 = pmulpmi<SIGN>(psub(v[2], v[6]));
    u64c E0 = padd(t0, t2), E1 = padd(t1, t3);
    u64c E2 = psub(t0, t2), E3 = psub(t1, t3);
    u64c u0 = padd(v[1], v[5]), u1 = psub(v[1], v[5]);
    u64c u2 = padd(v[3], v[7]), u3 = pmulpmi<SIGN>(psub(v[3], v[7]));
    u64c O0 = padd(u0, u2), O1 = padd(u1, u3);
    u64c O2 = psub(u0, u2), O3 = psub(u1, u3);
    O1 = pmulw81<SIGN>(O1);
    O2 = pmulpmi<SIGN>(O2);
    O3 = pmulw83<SIGN>(O3);
    v[0] = padd(E0, O0); v[4] = psub(E0, O0);
    v[1] = padd(E1, O1); v[5] = psub(E1, O1);
    v[2] = padd(E2, O2); v[6] = psub(E2, O2);
    v[3] = padd(E3, O3); v[7] = psub(E3, O3);
}

// Named barrier for the 64-thread FFT group f (ids 1..4; 0 = __syncthreads).
static __device__ __forceinline__ void gbar(int f) {
    asm volatile("bar.sync %0, 64;" :: "r"(f + 1) : "memory");
}

// 512-pt FFT, 64 threads per FFT (l in [0,64)), 8 points/thread, chunk f at
// offset f*CH in both buffers. Natural input bufA[f*CH+0..511], natural
// output bufB[f*CH+0..511]; bufA clobbered. All block threads MUST call
// (barriers inside); `active` masks work only. Caller syncs after fill.
// Inner exchanges are group-local -> named 64-thread barriers; final barrier
// block-wide (callers read across chunks).
// Layouts: phase1 out: [k0]-stride 66; phase2 out: [n0]-stride 68.
template<int SIGN>
static __device__ __forceinline__ void fft512x(
    float2* bufA, float2* bufB, int f, int l, const float2* tw, bool active)
{
    const int base = f * CH;
    u64c v[8];
    if (active) {
        #pragma unroll
        for (int e = 0; e < 8; ++e) v[e] = pk(bufA[base + l + 64*e]);
        fft8p<SIGN>(v);                              // over n2 -> k0
        const int n1 = l >> 3;
        #pragma unroll
        for (int k0 = 1; k0 < 8; ++k0)               // W64^{n1 k0}
            v[k0] = pcmul(v[k0], twl<SIGN>(tw, 8 * n1 * k0));
        #pragma unroll
        for (int k0 = 0; k0 < 8; ++k0) bufB[base + 66*k0 + l] = upk(v[k0]);
    }
    gbar(f);
    {
        const int k0 = l & 7, n0 = l >> 3;
        if (active) {
            #pragma unroll
            for (int n1 = 0; n1 < 8; ++n1) v[n1] = pk(bufB[base + 66*k0 + 8*n1 + n0]);
            fft8p<SIGN>(v);                          // over n1 -> k1
            #pragma unroll
            for (int k1 = 0; k1 < 8; ++k1)           // W512^{n0 (k0 + 8 k1)}
                v[k1] = pcmul(v[k1], twl<SIGN>(tw, n0 * (k0 + 8*k1)));
            #pragma unroll
            for (int k1 = 0; k1 < 8; ++k1) bufA[base + 68*n0 + 8*k1 + k0] = upk(v[k1]);
        }
    }
    gbar(f);
    if (active) {
        #pragma unroll
        for (int n0 = 0; n0 < 8; ++n0) v[n0] = pk(bufA[base + 68*n0 + l]);
        fft8p<SIGN>(v);                              // over n0 -> k2
        #pragma unroll
        for (int k2 = 0; k2 < 8; ++k2) bufB[base + 64*k2 + l] = upk(v[k2]);
    }
    __syncthreads();
}

// ---------------------------------------------------------------------------
// k0: DPLR generator, grid=1024 x 256. 8 rows (k1, per warp) x 32 cols (m,
//     per lane) -> coalesced stores. Omega via sincosf (keeps 1+Omega != 0
//     at Nyquist, matching the f32 reference). Pair-batched reciprocals with
//     2^-24 scaling (overflow-free). Pole accumulation in packed f32x2:
//     acc += (rx,rx)*(v.x,v.y) + (p,-p)*(v.y,v.x), r = (rx, -p).
//     Blocks 0,1 fill global twiddle tables.
// ---------------------------------------------------------------------------
#define TPB0 256
__global__ void k0_gen(const float* __restrict__ Lre, const float* __restrict__ Lim,
                       const float* __restrict__ Pre, const float* __restrict__ Pim,
                       const float* __restrict__ Bre, const float* __restrict__ Bim,
                       const float* __restrict__ Cri, const float* __restrict__ ls) {
    __shared__ float sLre[64], sLim[64];
    __shared__ u64c  sv[4][64], svs[4][64];   // packed (x,y) and swapped (y,x)
    const int t = threadIdx.x;
    const int b = blockIdx.x;
    if (b == 0) {
        for (int k = t; k < 512; k += TPB0) {
            float s, c; sincospif(-2.0f * (float)k / 512.0f, &s, &c);
            gtw512g[k] = make_float2(c, s);
        }
    } else if (b == 1) {
        for (int k = t; k < 512; k += TPB0) {
            float s, c; sincospif(-2.0f * (float)k / 1024.0f, &s, &c);
            gtw1024g[k] = make_float2(c, s);
        }
    }
    if (t < 64) {
        float2 Pv = make_float2(Pre[t], Pim[t]);
        float2 Bv = make_float2(Bre[t], Bim[t]);
        float2 Cj = make_float2(Cri[2*t], -Cri[2*t+1]);   // conj(C)
        float2 Pj = make_float2(Pv.x, -Pv.y);             // conj(P) (Q = P)
        sLre[t] = Lre[t]; sLim[t] = Lim[t];
        float2 v0 = cmul(Cj, Bv), v1 = cmul(Cj, Pv);
        float2 v2 = cmul(Pj, Bv), v3 = cmul(Pj, Pv);
        sv[0][t] = pk(v0); svs[0][t] = pk(make_float2(v0.y, v0.x));
        sv[1][t] = pk(v1); svs[1][t] = pk(make_float2(v1.y, v1.x));
        sv[2][t] = pk(v2); svs[2][t] = pk(make_float2(v2.y, v2.x));
        sv[3][t] = pk(v3); svs[3][t] = pk(make_float2(v3.y, v3.x));
    }
    __syncthreads();

    const int k1 = (b & 63) * 8 + (t >> 5);
    const int m  = (b >> 6) * 32 + (t & 31);
    const int j  = k1 + (m << 9);
    const float step = expf(ls[0]);

    float ang = -PI2 * ((float)j / (float)L_SIZE);
    float sn, cs; sincosf(ang, &sn, &cs);          // Omega = cs + i*sn
    float2 onem = make_float2(1.f - cs, -sn);
    float2 onep = make_float2(1.f + cs,  sn);
    float invp = 1.f / (onep.x*onep.x + onep.y*onep.y);
    float2 cc = make_float2(2.f*onep.x*invp, -2.f*onep.y*invp);  // 2/(1+Om)
    float2 qv = cmul(onem, make_float2(onep.x, -onep.y));
    float sfac = (2.f / step) * invp;
    float gx = qv.x * sfac, gy = qv.y * sfac;

    const float S = 5.9604644775390625e-8f;        // 2^-24
    u64c a00 = 0ull, a01 = 0ull, a10 = 0ull, a11 = 0ull;   // pk(0,0)
    #pragma unroll
    for (int q = 0; q < 32; ++q) {
        const int n = 2*q;
        float dx0 = gx - sLre[n],   dy0 = gy - sLim[n];
        float dx1 = gx - sLre[n+1], dy1 = gy - sLim[n+1];
        float b0 = fmaf(dx0, dx0, dy0*dy0) * S;
        float b1 = fmaf(dx1, dx1, dy1*dy1) * S;
        float tq = 1.f / (b0 * b1);
        float i0 = b1 * tq * S;                    // = 1/(dx0^2+dy0^2)
        float i1 = b0 * tq * S;
        float rx0 = dx0*i0, p0 = dy0*i0;           // r0 = (rx0, -p0)
        float rx1 = dx1*i1, p1 = dy1*i1;
        u64c pa0 = pk(make_float2(rx0,  rx0));
        u64c pb0 = pk(make_float2(p0,  -p0));
        u64c pa1 = pk(make_float2(rx1,  rx1));
        u64c pb1 = pk(make_float2(p1,  -p1));
        a00 = pfma(pa0, sv[0][n], pfma(pb0, svs[0][n], a00));
        a01 = pfma(pa0, sv[1][n], pfma(pb0, svs[1][n], a01));
        a10 = pfma(pa0, sv[2][n], pfma(pb0, svs[2][n], a10));
        a11 = pfma(pa0, sv[3][n], pfma(pb0, svs[3][n], a11));
        a00 = pfma(pa1, sv[0][n+1], pfma(pb1, svs[0][n+1], a00));
        a01 = pfma(pa1, sv[1][n+1], pfma(pb1, svs[1][n+1], a01));
        a10 = pfma(pa1, sv[2][n+1], pfma(pb1, svs[2][n+1], a10));
        a11 = pfma(pa1, sv[3][n+1], pfma(pb1, svs[3][n+1], a11));
    }
    float2 k00 = upk(a00), k01 = upk(a01), k10 = upk(a10), k11 = upk(a11);
    float2 den = make_float2(1.f + k11.x, k11.y);
    float invd = 1.f / (den.x*den.x + den.y*den.y);
    float2 num = cmul(k01, k10);
    float2 tq2 = cmul(num, make_float2(den.x*invd, -den.y*invd));
    float2 at  = cmul(cc, make_float2(k00.x - tq2.x, k00.y - tq2.y));

    dA[k1 * 512 + m] = at;
}

// ---------------------------------------------------------------------------
// k1: IFFT_L row pass (2 rows/block, TPB=128) + twiddle -> dB. grid=256
// ---------------------------------------------------------------------------
#define TPB1 128
__global__ void k1_rowfft() {
    __shared__ __align__(16) float2 sa[2*CH], sb[2*CH];
    __shared__ float2 tw[512];
    const int t = threadIdx.x;
    for (int i = t; i < 512; i += TPB1) tw[i] = gtw512g[i];
    const int row0 = blockIdx.x * 2;
    const float4* src = (const float4*)(dA + row0 * 512);
    for (int i = t; i < 512; i += TPB1) {
        int g = i >> 8, m2 = i & 255;
        float4 x = src[i];
        *(float4*)&sa[g*CH + 2*m2] = x;
    }
    __syncthreads();
    fft512x<+1>(sa, sb, t >> 6, t & 63, tw, true);
    for (int i = t; i < 512; i += TPB1) {
        int g = i >> 8, m2 = i & 255, m = 2*m2;
        int kk = row0 + g;
        float2 y0 = cmul(sb[g*CH + m],     twiddle_c((m*kk) & (L_SIZE-1),     L_SIZE, 1.0f));
        float2 y1 = cmul(sb[g*CH + m + 1], twiddle_c(((m+1)*kk) & (L_SIZE-1), L_SIZE, 1.0f));
        *(float4*)&dB[kk * 512 + m] = make_float4(y0.x, y0.y, y1.x, y1.y);
    }
}

// ---------------------------------------------------------------------------
// k23 FUSED: columns m0, m0+1 (grid=256, TPB=256).
//   Phase A: IFFT512 of dB cols (2 FFTs, threads<128) -> K; threads>=128
//            prefetch the strided u-gather into smem meanwhile.
//   Phase B: z = u + i*K for c = m and c = m+512; 4 fwd FFTs + fwd twiddle
//            -> dA[k1*1024 + c].
// ---------------------------------------------------------------------------
#define TPB23 256
__global__ void k23_cols(const float* __restrict__ u) {
    __shared__ __align__(16) float2 sa[4*CH], sb[4*CH];
    __shared__ float2 tw[512];
    __shared__ float su[4*260];
    const int m0 = blockIdx.x * 2;
    const int t = threadIdx.x;
    for (int i = t; i < 512; i += TPB23) tw[i] = gtw512g[i];
    for (int i = t; i < 512; i += TPB23) {
        float4 x = *(const float4*)(dB + i * 512 + m0);
        sa[0*CH + i] = make_float2(x.x, x.y);
        sa[1*CH + i] = make_float2(x.z, x.w);
    }
    __syncthreads();
    if (t >= 128) {
        for (int i = t - 128; i < 1024; i += 128) {
            int fp = i & 3, rr = i >> 2;
            int c = m0 + (fp & 1) + (fp >> 1) * 512;
            su[fp * 260 + rr] = u[rr * 1024 + c];
        }
    }
    fft512x<+1>(sa, sb, t >> 6, t & 63, tw, t < 128);
    const float invL = 1.0f / (float)L_SIZE;
    for (int i = t; i < 2048; i += TPB23) {
        int fp = i >> 9, rr = i & 511;
        int half = fp >> 1, f = fp & 1;
        float2 z = make_float2(0.f, 0.f);
        if (rr < 256) {
            float kv = sb[f*CH + 2*rr + half].x * invL;
            z = make_float2(su[fp * 260 + rr], kv);
        }
        sa[fp*CH + rr] = z;
    }
    __syncthreads();
    fft512x<-1>(sa, sb, t >> 6, t & 63, tw, true);
    for (int i = t; i < 2048; i += TPB23) {
        int fp = i & 3, k1 = i >> 2;
        int half = fp >> 1, f = fp & 1;
        int c = m0 + f + half * 512;
        int mm = (c * k1) & (N2L - 1);
        dA[k1 * 1024 + c] = cmul(sb[fp*CH + k1], twiddle_c(mm, N2L, -1.0f));
    }
}

// ---------------------------------------------------------------------------
// k4: paired rows (k1, 512-k1); block 0 takes self-paired rows {0,256}.
//   fwd FFT1024 x2 via radix-2 split (chunk fp = slot*2+h holds Z[2r+h]).
//   Pointwise S = U*Kd (Hermitian split). REAL-OUTPUT trick:
//   T[kc] = (S[k]+S[k+L])/2 + i w^k (S[k]-S[k+L])/2, k = rowk1 + 512 kc,
//   w = e^{+2pi i/2L}. One FFT512^{+} per slot on T + W_L^{+m k1} twiddle
//   -> dB[k1*512 + m]   (dB = 512x512 L-point four-step intermediate).
// ---------------------------------------------------------------------------
#define TPB4 256
__global__ void k4_mega() {
    __shared__ __align__(16) float2 sa[4*CH], sb[4*CH];
    __shared__ float2 tw[512], twh[512];
    const int t = threadIdx.x;
    for (int i = t; i < 512; i += TPB4) { tw[i] = gtw512g[i]; twh[i] = gtw1024g[i]; }
    const int b = blockIdx.x;
    const int rowA = b;
    const int rowB = (b == 0) ? 256 : 512 - b;

    for (int i = t; i < 1024; i += TPB4) {
        int slot = i >> 9, m2 = i & 511;
        int row = slot ? rowB : rowA;
        float4 x = ((const float4*)(dA + row * 1024))[m2];
        *(float4*)&sb[slot * 1024 + 2*m2] = x;
    }
    __syncthreads();
    // radix-2 pre-stage into chunks fp = slot*2 + h
    for (int i = t; i < 1024; i += TPB4) {
        int slot = i >> 9, m = i & 511;
        float2 a = sb[slot * 1024 + m];
        float2 c = sb[slot * 1024 + m + 512];
        sa[(slot*2 + 0)*CH + m] = cadd(a, c);
        sa[(slot*2 + 1)*CH + m] = cmul(csub(a, c), twh[m]);
    }
    __syncthreads();
    fft512x<-1>(sa, sb, t >> 6, t & 63, tw, true);
    // sb chunk fp, pos r  <->  Z[2r + (fp&1)] of row slot = fp>>1.
    // Pointwise S = U*Kd -> sa (same layout).
    for (int i = t; i < 2048; i += TPB4) {
        int fp = i >> 9, r = i & 511;
        int slot = fp >> 1, h = fp & 1;
        int k = 2*r + h;
        int pslot, pk_;
        if (b == 0) {
            pslot = slot;
            pk_ = slot ? (1023 - k) : ((1024 - k) & 1023);
        } else {
            pslot = 1 - slot;
            pk_ = 1023 - k;
        }
        float2 Zv = sb[fp*CH + r];
        float2 Zp = sb[(pslot*2 + (pk_ & 1))*CH + (pk_ >> 1)];
        float2 U  = make_float2(0.5f * (Zv.x + Zp.x),  0.5f * (Zv.y - Zp.y));
        float2 Kd = make_float2(0.5f * (Zv.y + Zp.y), -0.5f * (Zv.x - Zp.x));
        sa[fp*CH + r] = cmul(U, Kd);
    }
    __syncthreads();
    // Build T rows: S[k1+512 kc] at chunk (slot*2 + (kc&1)), pos kc>>1;
    // S[k1+512(kc+512)] at same chunk, pos (kc>>1)+256. T -> sb chunk slot.
    for (int i = t; i < 1024; i += TPB4) {
        int slot = i >> 9, kc = i & 511;
        int h = kc & 1, r0 = kc >> 1;
        int cb = (slot*2 + h)*CH;
        float2 S1 = sa[cb + r0];
        float2 S2 = sa[cb + r0 + 256];
        float2 E = make_float2(0.5f*(S1.x + S2.x), 0.5f*(S1.y + S2.y));
        float2 d = make_float2(0.5f*(S1.x - S2.x), 0.5f*(S1.y - S2.y));
        int kk = slot ? rowB : rowA;
        float2 o = cmul(twiddle_c(kk + (kc << 9), N2L, 1.0f), d);   // w^k * d
        sb[slot*CH + kc] = make_float2(E.x - o.y, E.y + o.x);       // E + i*O
    }
    __syncthreads();
    fft512x<+1>(sb, sa, t >> 6, t & 63, tw, t < 128);   // out in sa chunks 0,1
    for (int i = t; i < 1024; i += TPB4) {
        int slot = i >> 9, m = i & 511;
        int kk = slot ? rowB : rowA;
        dB[kk * 512 + m] = cmul(sa[slot*CH + m],
                                twiddle_c((m*kk) & (L_SIZE-1), L_SIZE, 1.0f));
    }
}

// ---------------------------------------------------------------------------
// k5: column IFFT512 of the 512x512 matrix dB (2 cols/block, TPB=128,
//     grid=256). z2[p*512+m] = y[2n] + i y[2n+1], n = p*512+m, p < 256.
// ---------------------------------------------------------------------------
#define TPB5 128
__global__ void k5_inv_cols(const float* __restrict__ u, const float* __restrict__ Dp,
                            float* __restrict__ out) {
    __shared__ __align__(16) float2 sa[2*CH], sb[2*CH];
    __shared__ float2 tw[512];
    const int m0 = blockIdx.x * 2;
    const int t = threadIdx.x;
    for (int i = t; i < 512; i += TPB5) tw[i] = gtw512g[i];
    for (int i = t; i < 512; i += TPB5) {
        float4 x = *(const float4*)(dB + i * 512 + m0);
        sa[0*CH + i] = make_float2(x.x, x.y);
        sa[1*CH + i] = make_float2(x.z, x.w);
    }
    __syncthreads();
    fft512x<+1>(sa, sb, t >> 6, t & 63, tw, true);
    const float sc = 1.0f / (float)L_SIZE;
    const float Dv = Dp[0];
    for (int p = t; p < 256; p += TPB5) {
        float2 v0 = sb[0*CH + p];     // column m0   -> y[2n0], y[2n0+1]
        float2 v1 = sb[1*CH + p];     // column m0+1 -> y[2n0+2], y[2n0+3]
        int n2 = 2 * (p * 512 + m0);  // 16B-aligned (m0 even)
        float4 uu = *(const float4*)(u + n2);
        float4 o;
        o.x = fmaf(Dv, uu.x, v0.x * sc);
        o.y = fmaf(Dv, uu.y, v0.y * sc);
        o.z = fmaf(Dv, uu.z, v1.x * sc);
        o.w = fmaf(Dv, uu.w, v1.y * sc);
        *(float4*)(out + n2) = o;
    }
}

// ---------------------------------------------------------------------------
extern "C" void kernel_launch(void* const* d_in, const int* in_sizes, int n_in,
                              void* d_out, int out_size) {
    (void)in_sizes; (void)n_in; (void)out_size;
    const float* u   = (const float*)d_in[0];
    const float* Lre = (const float*)d_in[1];
    const float* Lim = (const float*)d_in[2];
    const float* Pre = (const float*)d_in[3];
    const float* Pim = (const float*)d_in[4];
    const float* Bre = (const float*)d_in[5];
    const float* Bim = (const float*)d_in[6];
    const float* Cri = (const float*)d_in[7];
    const float* Dp  = (const float*)d_in[8];
    const float* ls  = (const float*)d_in[9];
    float* out = (float*)d_out;

    k0_gen      <<<1024, TPB0>>>(Lre, Lim, Pre, Pim, Bre, Bim, Cri, ls);
    k1_rowfft   <<<256,  TPB1>>>();
    k23_cols    <<<256,  TPB23>>>(u);
    k4_mega     <<<256,  TPB4>>>();
    k5_inv_cols <<<256,  TPB5>>>(u, Dp, out);
}